// round 3
// baseline (speedup 1.0000x reference)
#include <cuda_runtime.h>

#define DIMN   256
#define NHEAD  8
#define HD     32
#define BB     8
#define NQ     512
#define NK     4096
#define SCALE  0.17677669529663687f  /* 32^-0.5 */

// Scratch (device globals: allocation-free per harness rules)
__device__ float g_q [BB * NQ * DIMN];            // 4 MB   [b, nq, h*HD+d]
__device__ float g_k [BB * NHEAD * NK * HD];      // 33.5MB [b,h,nk,d]
__device__ float g_v [BB * NHEAD * NK * HD];      // 33.5MB [b,h,nk,d]
__device__ float g_ao[BB * NQ * DIMN];            // 4 MB   [b, nq, h*HD+d]

// ---------------------------------------------------------------------------
// Packed fp32x2 helpers (Blackwell FFMA2 path — ptxas never auto-emits these)
// ---------------------------------------------------------------------------
typedef unsigned long long u64;

__device__ __forceinline__ u64 pack2(float x, float y) {
    u64 u;
    asm("mov.b64 %0, {%1, %2};"
        : "=l"(u) : "r"(__float_as_uint(x)), "r"(__float_as_uint(y)));
    return u;
}
__device__ __forceinline__ u64 splat2(float x) { return pack2(x, x); }

__device__ __forceinline__ float2 unpack2(u64 u) {
    unsigned lo, hi;
    asm("mov.b64 {%0, %1}, %2;" : "=r"(lo), "=r"(hi) : "l"(u));
    return make_float2(__uint_as_float(lo), __uint_as_float(hi));
}
__device__ __forceinline__ u64 ffma2(u64 a, u64 b, u64 c) {
    u64 d;
    asm("fma.rn.f32x2 %0, %1, %2, %3;" : "=l"(d) : "l"(a), "l"(b), "l"(c));
    return d;
}
__device__ __forceinline__ u64 fmul2(u64 a, u64 b) {
    u64 d;
    asm("mul.rn.f32x2 %0, %1, %2;" : "=l"(d) : "l"(a), "l"(b));
    return d;
}

// ---------------------------------------------------------------------------
// Generic fp32 GEMM body: C[M,N] = A[M,K] @ W[K,N] + bias[N]
// 64x64 block tile, 256 threads, 4x4 micro-tile (FFMA2: 4x2 packed), K-tile 16.
// ---------------------------------------------------------------------------
__device__ __forceinline__ void gemm_body(const float* __restrict__ A,
                                          const float* __restrict__ W,
                                          const float* __restrict__ bias,
                                          float* __restrict__ C,
                                          int M, int N, int K)
{
    __shared__ float As[16][68];
    __shared__ float Ws[16][68];
    const int tx = threadIdx.x & 15;
    const int ty = threadIdx.x >> 4;
    const int m0 = blockIdx.y * 64;
    const int n0 = blockIdx.x * 64;

    const int ar = threadIdx.x >> 2;        // 0..63
    const int ac = (threadIdx.x & 3) * 4;   // 0,4,8,12

    u64 acc[4][2] = {};                     // (0,0) bit pattern == (+0.f,+0.f)

    for (int k0 = 0; k0 < K; k0 += 16) {
        float4 av = *(const float4*)&A[(size_t)(m0 + ar) * K + k0 + ac];
        As[ac + 0][ar] = av.x;
        As[ac + 1][ar] = av.y;
        As[ac + 2][ar] = av.z;
        As[ac + 3][ar] = av.w;
        float4 wv = *(const float4*)&W[(size_t)(k0 + ty) * N + n0 + tx * 4];
        *(float4*)&Ws[ty][tx * 4] = wv;
        __syncthreads();
        #pragma unroll
        for (int k = 0; k < 16; k++) {
            float4 a4 = *(const float4*)&As[k][ty * 4];
            float4 w4 = *(const float4*)&Ws[k][tx * 4];
            u64 w01 = pack2(w4.x, w4.y);
            u64 w23 = pack2(w4.z, w4.w);
            u64 s0 = splat2(a4.x), s1 = splat2(a4.y);
            u64 s2 = splat2(a4.z), s3 = splat2(a4.w);
            acc[0][0] = ffma2(s0, w01, acc[0][0]);
            acc[0][1] = ffma2(s0, w23, acc[0][1]);
            acc[1][0] = ffma2(s1, w01, acc[1][0]);
            acc[1][1] = ffma2(s1, w23, acc[1][1]);
            acc[2][0] = ffma2(s2, w01, acc[2][0]);
            acc[2][1] = ffma2(s2, w23, acc[2][1]);
            acc[3][0] = ffma2(s3, w01, acc[3][0]);
            acc[3][1] = ffma2(s3, w23, acc[3][1]);
        }
        __syncthreads();
    }

    const float4 bv = *(const float4*)&bias[n0 + tx * 4];
    #pragma unroll
    for (int i = 0; i < 4; i++) {
        float2 c01 = unpack2(acc[i][0]);
        float2 c23 = unpack2(acc[i][1]);
        float4 o;
        o.x = c01.x + bv.x;
        o.y = c01.y + bv.y;
        o.z = c23.x + bv.z;
        o.w = c23.y + bv.w;
        *(float4*)&C[(size_t)(m0 + ty * 4 + i) * N + n0 + tx * 4] = o;
    }
}

__global__ __launch_bounds__(256) void gemm_q(const float* __restrict__ A,
                                              const float* __restrict__ W,
                                              const float* __restrict__ bias)
{
    gemm_body(A, W, bias, g_q, BB * NQ, DIMN, DIMN);
}

__global__ __launch_bounds__(256) void gemm_out(const float* __restrict__ W,
                                                const float* __restrict__ bias,
                                                float* __restrict__ C)
{
    gemm_body(g_ao, W, bias, C, BB * NQ, DIMN, DIMN);
}

// KV projection: A = pointcloud [B*NK, 256], W = Wkv [256, 512].
// Epilogue scatters columns [0,256) -> g_k[b,h,nk,d], [256,512) -> g_v.
__global__ __launch_bounds__(256) void gemm_kv(const float* __restrict__ A,
                                               const float* __restrict__ W,
                                               const float* __restrict__ bias)
{
    const int N = 2 * DIMN, K = DIMN;
    __shared__ float As[16][68];
    __shared__ float Ws[16][68];
    const int tx = threadIdx.x & 15;
    const int ty = threadIdx.x >> 4;
    const int m0 = blockIdx.y * 64;
    const int n0 = blockIdx.x * 64;

    const int ar = threadIdx.x >> 2;
    const int ac = (threadIdx.x & 3) * 4;

    u64 acc[4][2] = {};

    for (int k0 = 0; k0 < K; k0 += 16) {
        float4 av = *(const float4*)&A[(size_t)(m0 + ar) * K + k0 + ac];
        As[ac + 0][ar] = av.x;
        As[ac + 1][ar] = av.y;
        As[ac + 2][ar] = av.z;
        As[ac + 3][ar] = av.w;
        float4 wv = *(const float4*)&W[(size_t)(k0 + ty) * N + n0 + tx * 4];
        *(float4*)&Ws[ty][tx * 4] = wv;
        __syncthreads();
        #pragma unroll
        for (int k = 0; k < 16; k++) {
            float4 a4 = *(const float4*)&As[k][ty * 4];
            float4 w4 = *(const float4*)&Ws[k][tx * 4];
            u64 w01 = pack2(w4.x, w4.y);
            u64 w23 = pack2(w4.z, w4.w);
            u64 s0 = splat2(a4.x), s1 = splat2(a4.y);
            u64 s2 = splat2(a4.z), s3 = splat2(a4.w);
            acc[0][0] = ffma2(s0, w01, acc[0][0]);
            acc[0][1] = ffma2(s0, w23, acc[0][1]);
            acc[1][0] = ffma2(s1, w01, acc[1][0]);
            acc[1][1] = ffma2(s1, w23, acc[1][1]);
            acc[2][0] = ffma2(s2, w01, acc[2][0]);
            acc[2][1] = ffma2(s2, w23, acc[2][1]);
            acc[3][0] = ffma2(s3, w01, acc[3][0]);
            acc[3][1] = ffma2(s3, w23, acc[3][1]);
        }
        __syncthreads();
    }

    const int gc = n0 + tx * 4;             // 4-aligned, never crosses a 32-group
    const float4 bv = *(const float4*)&bias[gc];
    #pragma unroll
    for (int i = 0; i < 4; i++) {
        const int gm = m0 + ty * 4 + i;
        const int b  = gm >> 12;            // /4096
        const int nk = gm & (NK - 1);
        float2 c01 = unpack2(acc[i][0]);
        float2 c23 = unpack2(acc[i][1]);
        float4 o;
        o.x = c01.x + bv.x;
        o.y = c01.y + bv.y;
        o.z = c23.x + bv.z;
        o.w = c23.y + bv.w;
        float* dst;
        if (gc < DIMN) {
            const int h = gc >> 5, d = gc & 31;
            dst = &g_k[(((size_t)(b * NHEAD + h)) * NK + nk) * HD + d];
        } else {
            const int c = gc - DIMN;
            const int h = c >> 5, d = c & 31;
            dst = &g_v[(((size_t)(b * NHEAD + h)) * NK + nk) * HD + d];
        }
        *(float4*)dst = o;
    }
}

// ---------------------------------------------------------------------------
// Flash attention: one block per (q-tile of 64, h, b). 256 threads.
// S = (Q*SCALE) @ K^T  [64x64 tile], online softmax, O += P @ V.
// S-tile uses FFMA2 paired along k-columns; PV uses FFMA2 paired along k
// (V stored in smem as k-pair-interleaved: Vp[kk/2][d*2 + (kk&1)]).
// ---------------------------------------------------------------------------
__global__ __launch_bounds__(256) void attn_kernel()
{
    __shared__ float Qs[HD][68];    // [d][q]
    __shared__ float Ks[HD][68];    // [d][k]
    __shared__ float Vp[32][68];    // [kpair][d*2 + parity]
    __shared__ float Ps[64][68];    // [q][k]

    const int tx = threadIdx.x & 15;
    const int ty = threadIdx.x >> 4;
    const int q0 = blockIdx.x * 64;
    const int h  = blockIdx.y;
    const int b  = blockIdx.z;
    const int bh = b * NHEAD + h;

    // Load + transpose + scale Q tile [64 x 32]
    {
        const int e   = threadIdx.x * 8;
        const int row = e >> 5;
        const int d   = e & 31;
        const float* qp = &g_q[((size_t)(b * NQ + q0 + row)) * DIMN + h * HD + d];
        float4 q1 = *(const float4*)qp;
        float4 q2 = *(const float4*)(qp + 4);
        Qs[d + 0][row] = q1.x * SCALE;
        Qs[d + 1][row] = q1.y * SCALE;
        Qs[d + 2][row] = q1.z * SCALE;
        Qs[d + 3][row] = q1.w * SCALE;
        Qs[d + 4][row] = q2.x * SCALE;
        Qs[d + 5][row] = q2.y * SCALE;
        Qs[d + 6][row] = q2.z * SCALE;
        Qs[d + 7][row] = q2.w * SCALE;
    }

    float m_r[4], l_r[4];
    u64   o2[4][2];                 // packed (even-k, odd-k) partial sums
    #pragma unroll
    for (int i = 0; i < 4; i++) {
        m_r[i] = -1e30f;
        l_r[i] = 0.f;
        o2[i][0] = 0ull;
        o2[i][1] = 0ull;
    }

    const float* kbase = &g_k[(size_t)bh * NK * HD];
    const float* vbase = &g_v[(size_t)bh * NK * HD];

    for (int k0 = 0; k0 < NK; k0 += 64) {
        __syncthreads();   // protect Ks/Vp/Ps reuse from previous iteration
        {
            const int e   = threadIdx.x * 8;
            const int row = e >> 5;
            const int d   = e & 31;
            const float* kp = kbase + (size_t)(k0 + row) * HD + d;
            float4 k1 = *(const float4*)kp;
            float4 k2 = *(const float4*)(kp + 4);
            Ks[d + 0][row] = k1.x; Ks[d + 1][row] = k1.y;
            Ks[d + 2][row] = k1.z; Ks[d + 3][row] = k1.w;
            Ks[d + 4][row] = k2.x; Ks[d + 5][row] = k2.y;
            Ks[d + 6][row] = k2.z; Ks[d + 7][row] = k2.w;
            const float* vp = vbase + (size_t)(k0 + row) * HD + d;
            float4 v1 = *(const float4*)vp;
            float4 v2 = *(const float4*)(vp + 4);
            float* vd = &Vp[row >> 1][(row & 1)];
            vd[(d + 0) * 2] = v1.x; vd[(d + 1) * 2] = v1.y;
            vd[(d + 2) * 2] = v1.z; vd[(d + 3) * 2] = v1.w;
            vd[(d + 4) * 2] = v2.x; vd[(d + 5) * 2] = v2.y;
            vd[(d + 6) * 2] = v2.z; vd[(d + 7) * 2] = v2.w;
        }
        __syncthreads();

        // S tile: 4 rows x 4 cols per thread, FFMA2 paired along cols
        u64 s2[4][2] = {};
        #pragma unroll
        for (int d = 0; d < HD; d++) {
            float4 q4 = *(const float4*)&Qs[d][ty * 4];
            float4 k4 = *(const float4*)&Ks[d][tx * 4];
            u64 k01 = pack2(k4.x, k4.y);
            u64 k23 = pack2(k4.z, k4.w);
            u64 a0 = splat2(q4.x), a1 = splat2(q4.y);
            u64 a2 = splat2(q4.z), a3 = splat2(q4.w);
            s2[0][0] = ffma2(a0, k01, s2[0][0]);
            s2[0][1] = ffma2(a0, k23, s2[0][1]);
            s2[1][0] = ffma2(a1, k01, s2[1][0]);
            s2[1][1] = ffma2(a1, k23, s2[1][1]);
            s2[2][0] = ffma2(a2, k01, s2[2][0]);
            s2[2][1] = ffma2(a2, k23, s2[2][1]);
            s2[3][0] = ffma2(a3, k01, s2[3][0]);
            s2[3][1] = ffma2(a3, k23, s2[3][1]);
        }

        // Online softmax (row reduction over the 16 tx lanes, intra-warp)
        #pragma unroll
        for (int i = 0; i < 4; i++) {
            float2 sA = unpack2(s2[i][0]);
            float2 sB = unpack2(s2[i][1]);
            float mt = fmaxf(fmaxf(sA.x, sA.y), fmaxf(sB.x, sB.y));
            #pragma unroll
            for (int off = 8; off >= 1; off >>= 1)
                mt = fmaxf(mt, __shfl_xor_sync(0xffffffffu, mt, off));
            const float mn   = fmaxf(m_r[i], mt);
            const float corr = __expf(m_r[i] - mn);
            float p0 = __expf(sA.x - mn);
            float p1 = __expf(sA.y - mn);
            float p2 = __expf(sB.x - mn);
            float p3 = __expf(sB.y - mn);
            float4 pv = {p0, p1, p2, p3};
            *(float4*)&Ps[ty * 4 + i][tx * 4] = pv;
            float rs = (p0 + p1) + (p2 + p3);
            #pragma unroll
            for (int off = 8; off >= 1; off >>= 1)
                rs += __shfl_xor_sync(0xffffffffu, rs, off);
            l_r[i]  = l_r[i] * corr + rs;
            const u64 c2 = splat2(corr);
            o2[i][0] = fmul2(o2[i][0], c2);
            o2[i][1] = fmul2(o2[i][1], c2);
            m_r[i]  = mn;
        }
        __syncthreads();

        // O += P @ V, FFMA2 paired along k.
        // Vp[m][tx*4 .. +3] = (v[2m][c0], v[2m+1][c0], v[2m][c1], v[2m+1][c1])
        #pragma unroll
        for (int kk = 0; kk < 64; kk += 4) {
            const int m = kk >> 1;
            float4 vA = *(const float4*)&Vp[m    ][tx * 4];
            float4 vB = *(const float4*)&Vp[m + 1][tx * 4];
            u64 vA0 = pack2(vA.x, vA.y);   // col c0, k-pair m
            u64 vA1 = pack2(vA.z, vA.w);   // col c1, k-pair m
            u64 vB0 = pack2(vB.x, vB.y);   // col c0, k-pair m+1
            u64 vB1 = pack2(vB.z, vB.w);   // col c1, k-pair m+1
            #pragma unroll
            for (int i = 0; i < 4; i++) {
                float4 pr = *(const float4*)&Ps[ty * 4 + i][kk];
                u64 pA = pack2(pr.x, pr.y);
                u64 pB = pack2(pr.z, pr.w);
                o2[i][0] = ffma2(pA, vA0, o2[i][0]);
                o2[i][0] = ffma2(pB, vB0, o2[i][0]);
                o2[i][1] = ffma2(pA, vA1, o2[i][1]);
                o2[i][1] = ffma2(pB, vB1, o2[i][1]);
            }
        }
    }

    #pragma unroll
    for (int i = 0; i < 4; i++) {
        const float inv = 1.0f / l_r[i];
        float2 oc0 = unpack2(o2[i][0]);
        float2 oc1 = unpack2(o2[i][1]);
        float2 ov = {(oc0.x + oc0.y) * inv, (oc1.x + oc1.y) * inv};
        *(float2*)&g_ao[((size_t)(b * NQ + q0 + ty * 4 + i)) * DIMN
                        + h * HD + tx * 2] = ov;
    }
}

// ---------------------------------------------------------------------------
extern "C" void kernel_launch(void* const* d_in, const int* in_sizes, int n_in,
                              void* d_out, int out_size)
{
    const float* state = (const float*)d_in[0];
    const float* pc    = (const float*)d_in[1];
    const float* Wq    = (const float*)d_in[2];
    const float* bq    = (const float*)d_in[3];
    const float* Wkv   = (const float*)d_in[4];
    const float* bkv   = (const float*)d_in[5];
    const float* Wo    = (const float*)d_in[6];
    const float* bo    = (const float*)d_in[7];
    float* out = (float*)d_out;

    gemm_q<<<dim3(DIMN / 64, (BB * NQ) / 64), 256>>>(state, Wq, bq);
    gemm_kv<<<dim3((2 * DIMN) / 64, (BB * NK) / 64), 256>>>(pc, Wkv, bkv);
    attn_kernel<<<dim3(NQ / 64, NHEAD, BB), 256>>>();
    gemm_out<<<dim3(DIMN / 64, (BB * NQ) / 64), 256>>>(Wo, bo, out);
}

// round 4
// speedup vs baseline: 2.0465x; 2.0465x over previous
#include <cuda_runtime.h>
#include <cuda_bf16.h>

typedef unsigned int u32;
typedef unsigned short u16;

#define DIMN   256
#define NHEAD  8
#define HD     32
#define BB     8
#define NQ     512
#define NK     4096
#define SCALE  0.17677669529663687f

// bf16 hi/lo split scratch. Packed pairs (even idx in low 16 bits).
__device__ u32 g_qh[BB*NQ*DIMN/2];                  // [b*NQ+q][h*16+dpair], pre-scaled
__device__ u32 g_ql[BB*NQ*DIMN/2];
__device__ u32 g_kh[BB*NHEAD*(size_t)NK*HD/2];      // [(bh*NK+key)*16 + dpair]
__device__ u32 g_kl[BB*NHEAD*(size_t)NK*HD/2];
__device__ u16 g_vth[(size_t)BB*NHEAD*HD*NK];       // transposed [(bh*32+d)*NK + key]
__device__ u16 g_vtl[(size_t)BB*NHEAD*HD*NK];
__device__ float g_ao[BB*NQ*DIMN];                  // attention out fp32

// ---------------------------------------------------------------------------
__device__ __forceinline__ void split2(float x, float y, u32 &h, u32 &l)
{
    __nv_bfloat162 hv = __floats2bfloat162_rn(x, y);
    float rx = x - __bfloat162float(hv.x);
    float ry = y - __bfloat162float(hv.y);
    __nv_bfloat162 lv = __floats2bfloat162_rn(rx, ry);
    h = *reinterpret_cast<u32*>(&hv);
    l = *reinterpret_cast<u32*>(&lv);
}

__device__ __forceinline__ void mma_bf16(float* d, u32 a0, u32 a1, u32 a2, u32 a3,
                                         u32 b0, u32 b1)
{
    asm volatile(
        "mma.sync.aligned.m16n8k16.row.col.f32.bf16.bf16.f32 "
        "{%0,%1,%2,%3}, {%4,%5,%6,%7}, {%8,%9}, {%0,%1,%2,%3};\n"
        : "+f"(d[0]), "+f"(d[1]), "+f"(d[2]), "+f"(d[3])
        : "r"(a0), "r"(a1), "r"(a2), "r"(a3), "r"(b0), "r"(b1));
}

// ---------------------------------------------------------------------------
// GEMM (bf16x3): block = 128 thr (4 warps), tile 64m x 64n, K=256 in steps of 16.
// MODE 0: Q-proj -> g_qh/g_ql (scaled). MODE 1: KV-proj -> g_kh/g_kl + g_vt*.
// MODE 2: O-proj -> C (fp32, +bias), reads g_ao when A==nullptr.
// ---------------------------------------------------------------------------
template<int MODE>
__global__ __launch_bounds__(128) void gemm_mma(const float* __restrict__ A,
                                                const float* __restrict__ W,
                                                const float* __restrict__ bias,
                                                float* __restrict__ C, int ldw)
{
    __shared__ u32 AsH[64][12], AsL[64][12];
    __shared__ u32 WsH[64][12], WsL[64][12];
    const int t = threadIdx.x, lane = t & 31, wrp = t >> 5;
    const int gid = lane >> 2, tig = lane & 3;
    const long m0 = blockIdx.y * 64L;
    const int  n0 = blockIdx.x * 64;
    const float* Ap = (MODE == 2) ? (const float*)g_ao : A;

    float acc[8][4] = {};
    const int arow = t >> 1, acs = (t & 1) * 8;
    const int wn = t & 63, wks = (t >> 6) * 8;

    for (int k0 = 0; k0 < DIMN; k0 += 16) {
        {
            const float* ap = Ap + (m0 + arow) * DIMN + k0 + acs;
            float4 f0 = *(const float4*)ap, f1 = *(const float4*)(ap + 4);
            u32 h, l; const int c = acs >> 1;
            split2(f0.x, f0.y, h, l); AsH[arow][c+0] = h; AsL[arow][c+0] = l;
            split2(f0.z, f0.w, h, l); AsH[arow][c+1] = h; AsL[arow][c+1] = l;
            split2(f1.x, f1.y, h, l); AsH[arow][c+2] = h; AsL[arow][c+2] = l;
            split2(f1.z, f1.w, h, l); AsH[arow][c+3] = h; AsL[arow][c+3] = l;
        }
        {
            const float* wp = W + (long)(k0 + wks) * ldw + n0 + wn;
            float w0 = wp[0],       w1 = wp[(long)ldw],   w2 = wp[2L*ldw], w3 = wp[3L*ldw];
            float w4 = wp[4L*ldw],  w5 = wp[5L*ldw],      w6 = wp[6L*ldw], w7 = wp[7L*ldw];
            u32 h, l; const int c = wks >> 1;
            split2(w0, w1, h, l); WsH[wn][c+0] = h; WsL[wn][c+0] = l;
            split2(w2, w3, h, l); WsH[wn][c+1] = h; WsL[wn][c+1] = l;
            split2(w4, w5, h, l); WsH[wn][c+2] = h; WsL[wn][c+2] = l;
            split2(w6, w7, h, l); WsH[wn][c+3] = h; WsL[wn][c+3] = l;
        }
        __syncthreads();
        const int r0 = wrp * 16 + gid;
        u32 ah0 = AsH[r0][tig],   ah1 = AsH[r0+8][tig];
        u32 ah2 = AsH[r0][tig+4], ah3 = AsH[r0+8][tig+4];
        u32 al0 = AsL[r0][tig],   al1 = AsL[r0+8][tig];
        u32 al2 = AsL[r0][tig+4], al3 = AsL[r0+8][tig+4];
        #pragma unroll
        for (int nt = 0; nt < 8; nt++) {
            u32 bh0 = WsH[nt*8+gid][tig], bh1 = WsH[nt*8+gid][tig+4];
            u32 bl0 = WsL[nt*8+gid][tig], bl1 = WsL[nt*8+gid][tig+4];
            mma_bf16(acc[nt], ah0, ah1, ah2, ah3, bh0, bh1);
            mma_bf16(acc[nt], al0, al1, al2, al3, bh0, bh1);
            mma_bf16(acc[nt], ah0, ah1, ah2, ah3, bl0, bl1);
        }
        __syncthreads();
    }

    const long mrow = m0 + wrp * 16 + gid;
    #pragma unroll
    for (int nt = 0; nt < 8; nt++) {
        const int col = n0 + nt * 8 + 2 * tig;
        const float b0v = bias[col], b1v = bias[col + 1];
        float v00 = acc[nt][0] + b0v, v01 = acc[nt][1] + b1v;
        float v10 = acc[nt][2] + b0v, v11 = acc[nt][3] + b1v;
        if (MODE == 0) {
            u32 h, l;
            split2(v00 * SCALE, v01 * SCALE, h, l);
            g_qh[mrow*128 + (col>>1)] = h;     g_ql[mrow*128 + (col>>1)] = l;
            split2(v10 * SCALE, v11 * SCALE, h, l);
            g_qh[(mrow+8)*128 + (col>>1)] = h; g_ql[(mrow+8)*128 + (col>>1)] = l;
        } else if (MODE == 2) {
            *(float2*)&C[mrow*DIMN + col]     = make_float2(v00, v01);
            *(float2*)&C[(mrow+8)*DIMN + col] = make_float2(v10, v11);
        } else {
            const int bb = (int)(mrow >> 12), key = (int)(mrow & (NK - 1));
            if (n0 < DIMN) {
                const int hh = col >> 5, dp = (col & 31) >> 1;
                u32 h, l;
                size_t i0 = ((size_t)(bb*NHEAD+hh)*NK + key) * 16 + dp;
                split2(v00, v01, h, l); g_kh[i0] = h; g_kl[i0] = l;
                size_t i1 = ((size_t)(bb*NHEAD+hh)*NK + key + 8) * 16 + dp;
                split2(v10, v11, h, l); g_kh[i1] = h; g_kl[i1] = l;
            } else {
                const int c2 = col - DIMN, hh = c2 >> 5, d = c2 & 31;
                size_t base = ((size_t)(bb*NHEAD+hh)*HD + d) * NK + key;
                u32 h, l;
                split2(v00, v01, h, l);
                g_vth[base]      = (u16)(h & 0xffff); g_vth[base+NK]   = (u16)(h >> 16);
                g_vtl[base]      = (u16)(l & 0xffff); g_vtl[base+NK]   = (u16)(l >> 16);
                split2(v10, v11, h, l);
                g_vth[base+8]    = (u16)(h & 0xffff); g_vth[base+NK+8] = (u16)(h >> 16);
                g_vtl[base+8]    = (u16)(l & 0xffff); g_vtl[base+NK+8] = (u16)(l >> 16);
            }
        }
    }
}

// ---------------------------------------------------------------------------
// Flash attention (bf16x3 mma): block = 128 thr (4 warps), 64 q-rows per block,
// warp owns 16 q-rows. Grid (NQ/64, NHEAD, BB). K-tiles of 64 keys.
// ---------------------------------------------------------------------------
__global__ __launch_bounds__(128) void attn_mma()
{
    __shared__ u32 Ksh[64][20], Ksl[64][20];   // [key][dpair]
    __shared__ u32 Vsh[32][36], Vsl[32][36];   // [d][keypair]

    const int t = threadIdx.x, lane = t & 31, wrp = t >> 5;
    const int gid = lane >> 2, tig = lane & 3;
    const int q0 = blockIdx.x * 64, h = blockIdx.y, b = blockIdx.z;
    const int bh = b * NHEAD + h;

    // Q fragments for both k-steps (d 0..15, 16..31), resident whole kernel
    u32 qh[2][4], ql[2][4];
    {
        const long r0 = (long)(b * NQ + q0 + wrp * 16 + gid) * 128 + h * 16;
        #pragma unroll
        for (int s = 0; s < 2; s++) {
            qh[s][0] = g_qh[r0 + s*8 + tig];          ql[s][0] = g_ql[r0 + s*8 + tig];
            qh[s][1] = g_qh[r0 + 1024 + s*8 + tig];   ql[s][1] = g_ql[r0 + 1024 + s*8 + tig];
            qh[s][2] = g_qh[r0 + s*8 + tig + 4];      ql[s][2] = g_ql[r0 + s*8 + tig + 4];
            qh[s][3] = g_qh[r0 + 1024 + s*8 + tig+4]; ql[s][3] = g_ql[r0 + 1024 + s*8 + tig+4];
        }
    }

    float mA = -1e30f, mB = -1e30f, lA = 0.f, lB = 0.f;
    float oacc[4][4] = {};

    const size_t kbase = (size_t)bh * NK * 16;          // u32 units
    const size_t vbase = (size_t)bh * HD * (NK / 2);    // u32 units
    const u32* vt_h = (const u32*)g_vth;
    const u32* vt_l = (const u32*)g_vtl;
    const int krow = t >> 1, kcs = (t & 1) * 8;
    const int vd = t >> 2,  vkp = (t & 3) * 8;

    for (int k0 = 0; k0 < NK; k0 += 64) {
        __syncthreads();
        {
            const u32* s0 = &g_kh[kbase + (size_t)(k0 + krow) * 16 + kcs];
            *(uint4*)&Ksh[krow][kcs]   = *(const uint4*)s0;
            *(uint4*)&Ksh[krow][kcs+4] = *(const uint4*)(s0 + 4);
            const u32* s1 = &g_kl[kbase + (size_t)(k0 + krow) * 16 + kcs];
            *(uint4*)&Ksl[krow][kcs]   = *(const uint4*)s1;
            *(uint4*)&Ksl[krow][kcs+4] = *(const uint4*)(s1 + 4);
            const u32* s2 = vt_h + vbase + (size_t)vd * (NK/2) + (k0 >> 1) + vkp;
            *(uint4*)&Vsh[vd][vkp]   = *(const uint4*)s2;
            *(uint4*)&Vsh[vd][vkp+4] = *(const uint4*)(s2 + 4);
            const u32* s3 = vt_l + vbase + (size_t)vd * (NK/2) + (k0 >> 1) + vkp;
            *(uint4*)&Vsl[vd][vkp]   = *(const uint4*)s3;
            *(uint4*)&Vsl[vd][vkp+4] = *(const uint4*)(s3 + 4);
        }
        __syncthreads();

        // S = Q @ K^T (3 passes, 2 k-steps)
        float sacc[8][4] = {};
        #pragma unroll
        for (int nt = 0; nt < 8; nt++) {
            const int kr = nt * 8 + gid;
            u32 b00 = Ksh[kr][tig],   b01 = Ksh[kr][tig+4];
            u32 b10 = Ksh[kr][tig+8], b11 = Ksh[kr][tig+12];
            u32 c00 = Ksl[kr][tig],   c01 = Ksl[kr][tig+4];
            u32 c10 = Ksl[kr][tig+8], c11 = Ksl[kr][tig+12];
            mma_bf16(sacc[nt], qh[0][0], qh[0][1], qh[0][2], qh[0][3], b00, b01);
            mma_bf16(sacc[nt], ql[0][0], ql[0][1], ql[0][2], ql[0][3], b00, b01);
            mma_bf16(sacc[nt], qh[0][0], qh[0][1], qh[0][2], qh[0][3], c00, c01);
            mma_bf16(sacc[nt], qh[1][0], qh[1][1], qh[1][2], qh[1][3], b10, b11);
            mma_bf16(sacc[nt], ql[1][0], ql[1][1], ql[1][2], ql[1][3], b10, b11);
            mma_bf16(sacc[nt], qh[1][0], qh[1][1], qh[1][2], qh[1][3], c10, c11);
        }

        // Online softmax: rows gid (A) and gid+8 (B); reduce across tig lanes
        float mtA = -1e30f, mtB = -1e30f;
        #pragma unroll
        for (int nt = 0; nt < 8; nt++) {
            mtA = fmaxf(mtA, fmaxf(sacc[nt][0], sacc[nt][1]));
            mtB = fmaxf(mtB, fmaxf(sacc[nt][2], sacc[nt][3]));
        }
        mtA = fmaxf(mtA, __shfl_xor_sync(0xffffffffu, mtA, 1));
        mtA = fmaxf(mtA, __shfl_xor_sync(0xffffffffu, mtA, 2));
        mtB = fmaxf(mtB, __shfl_xor_sync(0xffffffffu, mtB, 1));
        mtB = fmaxf(mtB, __shfl_xor_sync(0xffffffffu, mtB, 2));
        const float mnA = fmaxf(mA, mtA), mnB = fmaxf(mB, mtB);
        const float corrA = __expf(mA - mnA), corrB = __expf(mB - mnB);

        u32 pha[4][4], pla[4][4];
        float rsA = 0.f, rsB = 0.f;
        #pragma unroll
        for (int tt = 0; tt < 4; tt++) {
            #pragma unroll
            for (int u = 0; u < 2; u++) {
                const int nt = 2 * tt + u;
                float p0 = __expf(sacc[nt][0] - mnA);
                float p1 = __expf(sacc[nt][1] - mnA);
                float p2 = __expf(sacc[nt][2] - mnB);
                float p3 = __expf(sacc[nt][3] - mnB);
                rsA += p0 + p1; rsB += p2 + p3;
                u32 hh, ll;
                split2(p0, p1, hh, ll); pha[tt][u*2]   = hh; pla[tt][u*2]   = ll;
                split2(p2, p3, hh, ll); pha[tt][u*2+1] = hh; pla[tt][u*2+1] = ll;
            }
        }
        rsA += __shfl_xor_sync(0xffffffffu, rsA, 1);
        rsA += __shfl_xor_sync(0xffffffffu, rsA, 2);
        rsB += __shfl_xor_sync(0xffffffffu, rsB, 1);
        rsB += __shfl_xor_sync(0xffffffffu, rsB, 2);
        lA = lA * corrA + rsA;
        lB = lB * corrB + rsB;
        mA = mnA; mB = mnB;
        #pragma unroll
        for (int dnt = 0; dnt < 4; dnt++) {
            oacc[dnt][0] *= corrA; oacc[dnt][1] *= corrA;
            oacc[dnt][2] *= corrB; oacc[dnt][3] *= corrB;
        }

        // O += P @ V (3 passes, 4 k-steps of 16 keys)
        #pragma unroll
        for (int dnt = 0; dnt < 4; dnt++) {
            const int vr = dnt * 8 + gid;
            #pragma unroll
            for (int tt = 0; tt < 4; tt++) {
                u32 b0 = Vsh[vr][tt*8+tig], b1 = Vsh[vr][tt*8+tig+4];
                u32 c0 = Vsl[vr][tt*8+tig], c1 = Vsl[vr][tt*8+tig+4];
                mma_bf16(oacc[dnt], pha[tt][0], pha[tt][1], pha[tt][2], pha[tt][3], b0, b1);
                mma_bf16(oacc[dnt], pla[tt][0], pla[tt][1], pla[tt][2], pla[tt][3], b0, b1);
                mma_bf16(oacc[dnt], pha[tt][0], pha[tt][1], pha[tt][2], pha[tt][3], c0, c1);
            }
        }
    }

    const float invA = 1.f / lA, invB = 1.f / lB;
    const long orow = (long)(b * NQ + q0 + wrp * 16 + gid);
    #pragma unroll
    for (int dnt = 0; dnt < 4; dnt++) {
        const int col = h * HD + dnt * 8 + 2 * tig;
        *(float2*)&g_ao[orow*DIMN + col] =
            make_float2(oacc[dnt][0] * invA, oacc[dnt][1] * invA);
        *(float2*)&g_ao[(orow+8)*DIMN + col] =
            make_float2(oacc[dnt][2] * invB, oacc[dnt][3] * invB);
    }
}

// ---------------------------------------------------------------------------
extern "C" void kernel_launch(void* const* d_in, const int* in_sizes, int n_in,
                              void* d_out, int out_size)
{
    const float* state = (const float*)d_in[0];
    const float* pc    = (const float*)d_in[1];
    const float* Wq    = (const float*)d_in[2];
    const float* bq    = (const float*)d_in[3];
    const float* Wkv   = (const float*)d_in[4];
    const float* bkv   = (const float*)d_in[5];
    const float* Wo    = (const float*)d_in[6];
    const float* bo    = (const float*)d_in[7];
    float* out = (float*)d_out;

    gemm_mma<0><<<dim3(DIMN/64,   (BB*NQ)/64), 128>>>(state, Wq,  bq,  nullptr, DIMN);
    gemm_mma<1><<<dim3(2*DIMN/64, (BB*NK)/64), 128>>>(pc,    Wkv, bkv, nullptr, 2*DIMN);
    attn_mma<<<dim3(NQ/64, NHEAD, BB), 128>>>();
    gemm_mma<2><<<dim3(DIMN/64,   (BB*NQ)/64), 128>>>(nullptr, Wo, bo, out, DIMN);
}